// round 14
// baseline (speedup 1.0000x reference)
#include <cuda_runtime.h>
#include <cuda_bf16.h>
#include <stdint.h>
#include <math.h>

// ---------------------------------------------------------------------------
// PointNet++ grasp net forward. B=16, N=4096.
// FPS(both phases fused) -> SA1 -> U2(mma) -> SA2 -> SA3(mma) -> heads
// ---------------------------------------------------------------------------

#define BATCH 16
#define NPTS 4096

// exact f32 thresholds as JAX sees them (python double radius*radius -> f32)
#define R2A ((float)(0.2 * 0.2))
#define R2B ((float)(0.4 * 0.4))

// ------------------------- device scratch (static) -------------------------
__device__ __align__(16) float g_l1x[BATCH * 512 * 3];
__device__ __align__(16) float g_l1f[BATCH * 512 * 128];
__device__ __align__(16) float g_u2[BATCH * 512 * 128];   // l1f @ w20[3:] + b20
__device__ __align__(16) float g_l2x[BATCH * 128 * 3];
__device__ __align__(16) float g_l2f[BATCH * 128 * 256];
__device__ __align__(16) float g_h3a[BATCH * 128 * 256];
__device__ __align__(16) float g_h3b[BATCH * 128 * 512];
__device__ __align__(16) float g_pm[BATCH * 2 * 1024];    // 64-row maxpool partials

// ------------------------- mma / redux helpers -----------------------------
__device__ __forceinline__ uint32_t f2tf(float v) {
    uint32_t r;
    asm("cvt.rna.tf32.f32 %0, %1;" : "=r"(r) : "f"(v));
    return r;
}
__device__ __forceinline__ void mma_tf32(float* d, uint32_t a0, uint32_t a1,
                                         uint32_t a2, uint32_t a3,
                                         uint32_t b0, uint32_t b1) {
    asm volatile(
        "mma.sync.aligned.m16n8k8.row.col.f32.tf32.tf32.f32 "
        "{%0,%1,%2,%3}, {%4,%5,%6,%7}, {%8,%9}, {%0,%1,%2,%3};"
        : "+f"(d[0]), "+f"(d[1]), "+f"(d[2]), "+f"(d[3])
        : "r"(a0), "r"(a1), "r"(a2), "r"(a3), "r"(b0), "r"(b1));
}
__device__ __forceinline__ uint32_t redux_max_u32(uint32_t v) {
    uint32_t r;
    asm("redux.sync.max.u32 %0, %1, 0xffffffff;" : "=r"(r) : "r"(v));
    return r;
}
__device__ __forceinline__ uint32_t redux_min_u32(uint32_t v) {
    uint32_t r;
    asm("redux.sync.min.u32 %0, %1, 0xffffffff;" : "=r"(r) : "r"(v));
    return r;
}

// ---------------------------------------------------------------------------
// FPS, both phases in ONE kernel (one block per batch, 1024 threads).
// Phase 0: 4096 pts -> 512 samples (coords also captured in smem).
// Phase 1: those 512 -> 128 samples, run immediately (threads >=512 inert:
// they contribute val-bits 0 and idx 0xffffffff, which can never win).
// redux.sync on float bits (dist >= 0 so u32 order == float order); ties
// resolved by min index — exact jnp argmax semantics. No FMA fusion.
// ---------------------------------------------------------------------------
#define FPS_SMEM ((NPTS * 3 + 512 * 3 + 128) * 4)
extern __shared__ float fps_sm[];

__global__ __launch_bounds__(1024) void fps_kernel(const float* __restrict__ pts_in) {
    const int b = blockIdx.x;
    const float* p = pts_in + (size_t)b * NPTS * 3;

    const int tid = threadIdx.x, BT = 1024;
    float* sp = fps_sm;                        // 4096*3 point cache
    float* s2 = fps_sm + NPTS * 3;             // 512*3 sampled coords
    unsigned* rv = (unsigned*)(s2 + 512 * 3);  // 2x32 candidate val bits
    int* ri = (int*)(rv + 64);                 // 2x32 candidate idxs

    for (int e = tid; e < NPTS * 3; e += BT) sp[e] = p[e];

    float px[4], py[4], pz[4], dd[4];
#pragma unroll
    for (int k = 0; k < 4; k++) {
        int i = tid + k * BT;
        px[k] = p[i * 3 + 0];
        py[k] = p[i * 3 + 1];
        pz[k] = p[i * 3 + 2];
        dd[k] = 1e10f;
    }
    __syncthreads();

    const int lane = tid & 31, wid = tid >> 5;
    const int lsel = lane;  // 32 warps -> slot = lane
    int far = 0;

    // ---- phase 0: 4096 -> 512 ----
    for (int s = 0; s < 512; s++) {
        const float fx = sp[far * 3 + 0], fy = sp[far * 3 + 1], fz = sp[far * 3 + 2];
        if (tid == 0) {
            float* o = g_l1x + ((size_t)b * 512 + s) * 3;
            o[0] = fx; o[1] = fy; o[2] = fz;
            s2[s * 3 + 0] = fx; s2[s * 3 + 1] = fy; s2[s * 3 + 2] = fz;
        }
        float bv = -1.0f;
        int bi = 0x7fffffff;
#pragma unroll
        for (int k = 0; k < 4; k++) {
            float dx = __fsub_rn(px[k], fx);
            float dy = __fsub_rn(py[k], fy);
            float dz = __fsub_rn(pz[k], fz);
            float d = __fadd_rn(__fadd_rn(__fmul_rn(dx, dx), __fmul_rn(dy, dy)),
                                __fmul_rn(dz, dz));
            float ndv = fminf(dd[k], d);
            dd[k] = ndv;
            if (ndv > bv) { bv = ndv; bi = tid + k * BT; }  // ascending k keeps min idx
        }
        {
            uint32_t uv = __float_as_uint(bv);  // bv >= 0 (dists >= 0)
            uint32_t vmax = redux_max_u32(uv);
            uint32_t ip = (uv == vmax) ? (uint32_t)bi : 0xffffffffu;
            uint32_t imin = redux_min_u32(ip);
            const int po = (s & 1) * 32;
            if (lane == 0) { rv[po + wid] = vmax; ri[po + wid] = (int)imin; }
        }
        __syncthreads();
        {
            const int po = (s & 1) * 32;
            uint32_t v = rv[po + lsel];
            int i2 = ri[po + lsel];
            uint32_t vmax = redux_max_u32(v);
            uint32_t ip = (v == vmax) ? (uint32_t)i2 : 0xffffffffu;
            far = (int)redux_min_u32(ip);
        }
    }
    __syncthreads();

    // ---- phase 1: 512 -> 128 (threads < 512 own one point each) ----
    const bool act = tid < 512;
    float qx = 0.f, qy = 0.f, qz = 0.f, qd = 1e10f;
    if (act) {
        qx = s2[tid * 3 + 0]; qy = s2[tid * 3 + 1]; qz = s2[tid * 3 + 2];
    }
    far = 0;
    for (int s = 0; s < 128; s++) {
        const float fx = s2[far * 3 + 0], fy = s2[far * 3 + 1], fz = s2[far * 3 + 2];
        if (tid == 0) {
            float* o = g_l2x + ((size_t)b * 128 + s) * 3;
            o[0] = fx; o[1] = fy; o[2] = fz;
        }
        uint32_t uv = 0u;
        int bi = 0x7fffffff;
        if (act) {
            float dx = __fsub_rn(qx, fx);
            float dy = __fsub_rn(qy, fy);
            float dz = __fsub_rn(qz, fz);
            float d = __fadd_rn(__fadd_rn(__fmul_rn(dx, dx), __fmul_rn(dy, dy)),
                                __fmul_rn(dz, dz));
            qd = fminf(qd, d);
            uv = __float_as_uint(qd);
            bi = tid;
        }
        {
            uint32_t vmax = redux_max_u32(uv);
            uint32_t ip = (uv == vmax) ? (uint32_t)bi : 0xffffffffu;
            uint32_t imin = redux_min_u32(ip);
            const int po = (s & 1) * 32;
            if (lane == 0) { rv[po + wid] = vmax; ri[po + wid] = (int)imin; }
        }
        __syncthreads();
        {
            const int po = (s & 1) * 32;
            uint32_t v = rv[po + lsel];
            int i2 = ri[po + lsel];
            uint32_t vmax = redux_max_u32(v);
            uint32_t ip = (v == vmax) ? (uint32_t)i2 : 0xffffffffu;
            far = (int)redux_min_u32(ip);
        }
    }
}

// ---------------------------------------------------------------------------
// SA1: FOUR groups per block (256 thr). Ball query r=0.2 ns=32 over 4096 pts
// amortized over 4 centers; L1 (3->64) scalar; L2/L3 on tf32 mma with fused
// per-group maxpool. 128 rows = 8 m16 tiles, warp = m-tile.
// ---------------------------------------------------------------------------
#define P1 68
#define SA1_SMEM ((384 + 16 + 2 * 128 * P1) * 4 + 4 * 128 * 4 + 128 * 4)

extern __shared__ float sa1_sm[];

__global__ __launch_bounds__(256) void sa1_kernel(
    const float* __restrict__ pts,
    const float* __restrict__ w10, const float* __restrict__ b10,
    const float* __restrict__ w11, const float* __restrict__ b11,
    const float* __restrict__ w12, const float* __restrict__ b12) {
    const int sp4 = blockIdx.x;
    const int b = blockIdx.y;
    const int tid = threadIdx.x;
    const float* p = pts + (size_t)b * NPTS * 3;

    float* Ax = sa1_sm;
    float* ctr = Ax + 384;
    float* H1 = ctr + 16;
    float* H2 = H1 + 128 * P1;
    unsigned* smask = (unsigned*)(H2 + 128 * P1);
    int* sel = (int*)(smask + 512);

    if (tid < 12) ctr[tid] = g_l1x[((size_t)b * 512 + sp4 * 4) * 3 + tid];
    __syncthreads();

    const int lane = tid & 31, warp = tid >> 5;
    {
        const float ax = ctr[0], ay = ctr[1], az = ctr[2];
        const float bx = ctr[3], by = ctr[4], bz = ctr[5];
        const float cx = ctr[6], cy = ctr[7], cz = ctr[8];
        const float ex = ctr[9], ey = ctr[10], ez = ctr[11];
        for (int w = warp; w < 128; w += 8) {
            int j = w * 32 + lane;
            float x = p[j * 3 + 0], y = p[j * 3 + 1], z = p[j * 3 + 2];
            float t0, t1, t2, d0, d1, d2, d3;
            t0 = __fsub_rn(ax, x); t1 = __fsub_rn(ay, y); t2 = __fsub_rn(az, z);
            d0 = __fadd_rn(__fadd_rn(__fmul_rn(t0, t0), __fmul_rn(t1, t1)), __fmul_rn(t2, t2));
            t0 = __fsub_rn(bx, x); t1 = __fsub_rn(by, y); t2 = __fsub_rn(bz, z);
            d1 = __fadd_rn(__fadd_rn(__fmul_rn(t0, t0), __fmul_rn(t1, t1)), __fmul_rn(t2, t2));
            t0 = __fsub_rn(cx, x); t1 = __fsub_rn(cy, y); t2 = __fsub_rn(cz, z);
            d2 = __fadd_rn(__fadd_rn(__fmul_rn(t0, t0), __fmul_rn(t1, t1)), __fmul_rn(t2, t2));
            t0 = __fsub_rn(ex, x); t1 = __fsub_rn(ey, y); t2 = __fsub_rn(ez, z);
            d3 = __fadd_rn(__fadd_rn(__fmul_rn(t0, t0), __fmul_rn(t1, t1)), __fmul_rn(t2, t2));
            unsigned m0 = __ballot_sync(0xffffffffu, !(d0 > R2A));
            unsigned m1 = __ballot_sync(0xffffffffu, !(d1 > R2A));
            unsigned m2 = __ballot_sync(0xffffffffu, !(d2 > R2A));
            unsigned m3 = __ballot_sync(0xffffffffu, !(d3 > R2A));
            if (lane == 0) {
                smask[w] = m0; smask[128 + w] = m1;
                smask[256 + w] = m2; smask[384 + w] = m3;
            }
        }
    }
    __syncthreads();
    if ((tid & 63) == 0) {
        int gs = tid >> 6;
        int cnt = 0;
        for (int w = 0; w < 128 && cnt < 32; w++) {
            unsigned m = smask[gs * 128 + w];
            while (m && cnt < 32) {
                int t = __ffs(m) - 1;
                m &= m - 1;
                sel[gs * 32 + cnt++] = w * 32 + t;
            }
        }
        int c0 = sel[gs * 32];
        for (int j = cnt; j < 32; j++) sel[gs * 32 + j] = c0;
    }
    __syncthreads();
    for (int e = tid; e < 384; e += 256) {
        int n = e / 3, c = e - n * 3;
        Ax[e] = p[sel[n] * 3 + c] - ctr[(n >> 5) * 3 + c];
    }
    __syncthreads();

    // L1: 3 -> 64 for 128 rows
#pragma unroll
    for (int r = 0; r < 32; r++) {
        int lin = r * 256 + tid;
        int n = lin >> 6, o = lin & 63;
        float a = b10[o] + Ax[n * 3 + 0] * w10[o] + Ax[n * 3 + 1] * w10[64 + o] +
                  Ax[n * 3 + 2] * w10[128 + o];
        H1[n * P1 + o] = fmaxf(a, 0.f);
    }
    __syncthreads();

    const int g = lane >> 2, q = lane & 3;
    const int m0 = warp * 16;

    // L2: 128x64x64 tf32 mma -> H2
    {
        float d[8][4] = {};
        for (int k0 = 0; k0 < 64; k0 += 8) {
            uint32_t a0 = f2tf(H1[(m0 + g) * P1 + k0 + q]);
            uint32_t a1 = f2tf(H1[(m0 + g + 8) * P1 + k0 + q]);
            uint32_t a2 = f2tf(H1[(m0 + g) * P1 + k0 + q + 4]);
            uint32_t a3 = f2tf(H1[(m0 + g + 8) * P1 + k0 + q + 4]);
#pragma unroll
            for (int nt = 0; nt < 8; nt++) {
                int n0 = nt * 8;
                uint32_t b0 = f2tf(w11[(k0 + q) * 64 + n0 + g]);
                uint32_t b1 = f2tf(w11[(k0 + q + 4) * 64 + n0 + g]);
                mma_tf32(d[nt], a0, a1, a2, a3, b0, b1);
            }
        }
        __syncthreads();
#pragma unroll
        for (int nt = 0; nt < 8; nt++) {
            int c0 = nt * 8 + q * 2;
            float bb0 = b11[c0], bb1 = b11[c0 + 1];
            H2[(m0 + g) * P1 + c0] = fmaxf(d[nt][0] + bb0, 0.f);
            H2[(m0 + g) * P1 + c0 + 1] = fmaxf(d[nt][1] + bb1, 0.f);
            H2[(m0 + g + 8) * P1 + c0] = fmaxf(d[nt][2] + bb0, 0.f);
            H2[(m0 + g + 8) * P1 + c0 + 1] = fmaxf(d[nt][3] + bb1, 0.f);
        }
    }
    __syncthreads();

    // L3: 128x128x64 tf32 mma in two 64-col passes with fused 16-row maxpool
    float* Pm = H1;  // [8][128]
    for (int pass = 0; pass < 2; pass++) {
        float d[8][4] = {};
        for (int k0 = 0; k0 < 64; k0 += 8) {
            uint32_t a0 = f2tf(H2[(m0 + g) * P1 + k0 + q]);
            uint32_t a1 = f2tf(H2[(m0 + g + 8) * P1 + k0 + q]);
            uint32_t a2 = f2tf(H2[(m0 + g) * P1 + k0 + q + 4]);
            uint32_t a3 = f2tf(H2[(m0 + g + 8) * P1 + k0 + q + 4]);
#pragma unroll
            for (int nt = 0; nt < 8; nt++) {
                int n0 = pass * 64 + nt * 8;
                uint32_t b0 = f2tf(w12[(k0 + q) * 128 + n0 + g]);
                uint32_t b1 = f2tf(w12[(k0 + q + 4) * 128 + n0 + g]);
                mma_tf32(d[nt], a0, a1, a2, a3, b0, b1);
            }
        }
#pragma unroll
        for (int nt = 0; nt < 8; nt++) {
            float m0v = fmaxf(d[nt][0], d[nt][2]);
            float m1v = fmaxf(d[nt][1], d[nt][3]);
#pragma unroll
            for (int off = 4; off < 32; off <<= 1) {
                m0v = fmaxf(m0v, __shfl_xor_sync(0xffffffffu, m0v, off));
                m1v = fmaxf(m1v, __shfl_xor_sync(0xffffffffu, m1v, off));
            }
            if (g == 0) {
                int c0 = pass * 64 + nt * 8 + q * 2;
                Pm[warp * 128 + c0] = m0v;
                Pm[warp * 128 + c0 + 1] = m1v;
            }
        }
    }
    __syncthreads();
    for (int e = tid; e < 512; e += 256) {
        int h = e >> 7, o = e & 127;
        float m = fmaxf(Pm[(2 * h) * 128 + o], Pm[(2 * h + 1) * 128 + o]);
        g_l1f[((size_t)b * 512 + sp4 * 4 + h) * 128 + o] = fmaxf(m + b12[o], 0.f);
    }
}

// ---------------------------------------------------------------------------
// SA2: TWO groups per block (128 rows). Ball query r=0.4 ns=64 over 512 pts
// amortized over 2 centers; L1 via U2 gather; L2 (128->128) and
// L3 (128->256, fused maxpool) on tf32 mma. warp = m-tile (16 rows), full n.
// ---------------------------------------------------------------------------
#define P2 132
#define SA2_SMEM ((128 * P2 + 8 * 256 + 8 + 384) * 4 + 32 * 4 + 128 * 4)

extern __shared__ float sa2_sm[];

__global__ __launch_bounds__(256) void sa2_kernel(
    const float* __restrict__ w20,
    const float* __restrict__ w21, const float* __restrict__ b21,
    const float* __restrict__ w22, const float* __restrict__ b22) {
    const int s2 = blockIdx.x;  // groups s2*2, s2*2+1
    const int b = blockIdx.y;
    const int tid = threadIdx.x;
    const float* px = g_l1x + (size_t)b * 512 * 3;

    float* H = sa2_sm;
    float* Pm = H + 128 * P2;
    float* ctr = Pm + 8 * 256;
    float* dx3 = ctr + 8;
    unsigned* smask = (unsigned*)(dx3 + 384);
    int* sel = (int*)(smask + 32);

    if (tid < 6) ctr[tid] = g_l2x[((size_t)b * 128 + s2 * 2) * 3 + tid];
    __syncthreads();

    const int lane = tid & 31, warp = tid >> 5;
    {
        const float ax = ctr[0], ay = ctr[1], az = ctr[2];
        const float bx = ctr[3], by = ctr[4], bz = ctr[5];
        for (int w = warp; w < 16; w += 8) {
            int j = w * 32 + lane;
            float x = px[j * 3 + 0], y = px[j * 3 + 1], z = px[j * 3 + 2];
            float t0, t1, t2, d0, d1;
            t0 = __fsub_rn(ax, x); t1 = __fsub_rn(ay, y); t2 = __fsub_rn(az, z);
            d0 = __fadd_rn(__fadd_rn(__fmul_rn(t0, t0), __fmul_rn(t1, t1)), __fmul_rn(t2, t2));
            t0 = __fsub_rn(bx, x); t1 = __fsub_rn(by, y); t2 = __fsub_rn(bz, z);
            d1 = __fadd_rn(__fadd_rn(__fmul_rn(t0, t0), __fmul_rn(t1, t1)), __fmul_rn(t2, t2));
            unsigned m0 = __ballot_sync(0xffffffffu, !(d0 > R2B));
            unsigned m1 = __ballot_sync(0xffffffffu, !(d1 > R2B));
            if (lane == 0) { smask[w] = m0; smask[16 + w] = m1; }
        }
    }
    __syncthreads();
    if (tid == 0 || tid == 128) {
        int gs = tid >> 7;
        int cnt = 0;
        for (int w = 0; w < 16 && cnt < 64; w++) {
            unsigned m = smask[gs * 16 + w];
            while (m && cnt < 64) {
                int t = __ffs(m) - 1;
                m &= m - 1;
                sel[gs * 64 + cnt++] = w * 32 + t;
            }
        }
        int c0 = sel[gs * 64];
        for (int j = cnt; j < 64; j++) sel[gs * 64 + j] = c0;
    }
    __syncthreads();
    for (int e = tid; e < 384; e += 256) {
        int n = e / 3, c = e - n * 3;
        dx3[e] = px[sel[n] * 3 + c] - ctr[(n >> 6) * 3 + c];
    }
    __syncthreads();

    // L1: gather U2 + xyz contribution, relu. 16 rows x 4 cols per thread.
    {
        const int o0 = (tid & 31) * 4, n0 = (tid >> 5) * 16;
        float4 wxv = *(const float4*)(w20 + o0);
        float4 wyv = *(const float4*)(w20 + 128 + o0);
        float4 wzv = *(const float4*)(w20 + 256 + o0);
#pragma unroll
        for (int i = 0; i < 16; i++) {
            int n = n0 + i;
            float ddx = dx3[n * 3 + 0], ddy = dx3[n * 3 + 1], ddz = dx3[n * 3 + 2];
            float4 u = *(const float4*)(g_u2 + ((size_t)b * 512 + sel[n]) * 128 + o0);
            float4 r;
            r.x = fmaxf(u.x + ddx * wxv.x + ddy * wyv.x + ddz * wzv.x, 0.f);
            r.y = fmaxf(u.y + ddx * wxv.y + ddy * wyv.y + ddz * wzv.y, 0.f);
            r.z = fmaxf(u.z + ddx * wxv.z + ddy * wyv.z + ddz * wzv.z, 0.f);
            r.w = fmaxf(u.w + ddx * wxv.w + ddy * wyv.w + ddz * wzv.w, 0.f);
            *(float4*)(H + n * P2 + o0) = r;
        }
    }
    __syncthreads();

    const int g = lane >> 2, q = lane & 3;
    const int m0 = warp * 16;

    // L2: 128x128x128 tf32 mma (warp = m-tile, full 128 cols), in-place H
    {
        float d[16][4] = {};
        for (int k0 = 0; k0 < 128; k0 += 8) {
            uint32_t a0 = f2tf(H[(m0 + g) * P2 + k0 + q]);
            uint32_t a1 = f2tf(H[(m0 + g + 8) * P2 + k0 + q]);
            uint32_t a2 = f2tf(H[(m0 + g) * P2 + k0 + q + 4]);
            uint32_t a3 = f2tf(H[(m0 + g + 8) * P2 + k0 + q + 4]);
#pragma unroll
            for (int nt = 0; nt < 16; nt++) {
                int n0 = nt * 8;
                uint32_t b0 = f2tf(w21[(k0 + q) * 128 + n0 + g]);
                uint32_t b1 = f2tf(w21[(k0 + q + 4) * 128 + n0 + g]);
                mma_tf32(d[nt], a0, a1, a2, a3, b0, b1);
            }
        }
        __syncthreads();
#pragma unroll
        for (int nt = 0; nt < 16; nt++) {
            int c0 = nt * 8 + q * 2;
            float bb0 = b21[c0], bb1 = b21[c0 + 1];
            H[(m0 + g) * P2 + c0] = fmaxf(d[nt][0] + bb0, 0.f);
            H[(m0 + g) * P2 + c0 + 1] = fmaxf(d[nt][1] + bb1, 0.f);
            H[(m0 + g + 8) * P2 + c0] = fmaxf(d[nt][2] + bb0, 0.f);
            H[(m0 + g + 8) * P2 + c0 + 1] = fmaxf(d[nt][3] + bb1, 0.f);
        }
    }
    __syncthreads();

    // L3: 128x256x128 tf32 mma in two 128-col passes, fused 16-row maxpool
    for (int pass = 0; pass < 2; pass++) {
        float d[16][4] = {};
        for (int k0 = 0; k0 < 128; k0 += 8) {
            uint32_t a0 = f2tf(H[(m0 + g) * P2 + k0 + q]);
            uint32_t a1 = f2tf(H[(m0 + g + 8) * P2 + k0 + q]);
            uint32_t a2 = f2tf(H[(m0 + g) * P2 + k0 + q + 4]);
            uint32_t a3 = f2tf(H[(m0 + g + 8) * P2 + k0 + q + 4]);
#pragma unroll
            for (int nt = 0; nt < 16; nt++) {
                int n0 = pass * 128 + nt * 8;
                uint32_t b0 = f2tf(w22[(k0 + q) * 256 + n0 + g]);
                uint32_t b1 = f2tf(w22[(k0 + q + 4) * 256 + n0 + g]);
                mma_tf32(d[nt], a0, a1, a2, a3, b0, b1);
            }
        }
#pragma unroll
        for (int nt = 0; nt < 16; nt++) {
            float m0v = fmaxf(d[nt][0], d[nt][2]);
            float m1v = fmaxf(d[nt][1], d[nt][3]);
#pragma unroll
            for (int off = 4; off < 32; off <<= 1) {
                m0v = fmaxf(m0v, __shfl_xor_sync(0xffffffffu, m0v, off));
                m1v = fmaxf(m1v, __shfl_xor_sync(0xffffffffu, m1v, off));
            }
            if (g == 0) {
                int c0 = pass * 128 + nt * 8 + q * 2;
                Pm[warp * 256 + c0] = m0v;
                Pm[warp * 256 + c0 + 1] = m1v;
            }
        }
    }
    __syncthreads();
    for (int e = tid; e < 512; e += 256) {
        int h = e >> 8, o = e & 255;
        float m = fmaxf(fmaxf(Pm[(4 * h) * 256 + o], Pm[(4 * h + 1) * 256 + o]),
                        fmaxf(Pm[(4 * h + 2) * 256 + o], Pm[(4 * h + 3) * 256 + o]));
        g_l2f[((size_t)b * 128 + s2 * 2 + h) * 256 + o] = fmaxf(m + b22[o], 0.f);
    }
}

// ---------------------------------------------------------------------------
// tf32 mma GEMM + bias (+relu), batch flattened into M. Inline weight loads
// (L2-resident, 4-way cross-warp reuse — staging measured slower in R12).
// which: 0 concat(l2x,l2f)->h3a (K=259,O=256), 1 h3a->h3b (256,512),
//        2 h3b->g_pm maxpool partials (512,1024), 3 l1f->u2 (128,128)
// ---------------------------------------------------------------------------
__global__ __launch_bounds__(256) void gemm_mma_kernel(const float* __restrict__ W,
                                                       const float* __restrict__ bias,
                                                       int K, int O, int which, int dorelu) {
    const int mblk = blockIdx.x, oblk = blockIdx.y;
    const float* A = nullptr;
    float* C = nullptr;
    if (which == 1) { A = g_h3a; C = g_h3b; }
    else if (which == 2) { A = g_h3b; }
    else if (which == 3) { A = g_l1f; C = g_u2; }
    else { C = g_h3a; }

    const int row0 = mblk * 64;
    const int tid = threadIdx.x, lane = tid & 31, warp = tid >> 5;
    const int g = lane >> 2, q = lane & 3;
    const int mi = warp >> 1, nh = warp & 1, m0 = mi * 16;
    const int ob = oblk * 64;

    __shared__ __align__(16) float As[64 * 36];
    __shared__ float Pms[4 * 64];
    float d[4][4] = {};
    for (int kb = 0; kb < K; kb += 32) {
        const int w = min(32, K - kb);
        __syncthreads();
        if (which == 0) {
            for (int e = tid; e < 64 * 32; e += 256) {
                int r = e >> 5, cc = e & 31;
                int col = kb + cc;
                float v = 0.f;
                if (col < K) {
                    int row = row0 + r, bb = row >> 7, nn = row & 127;
                    v = (col < 3) ? g_l2x[((size_t)bb * 128 + nn) * 3 + col]
                                  : g_l2f[((size_t)bb * 128 + nn) * 256 + col - 3];
                }
                As[r * 36 + cc] = v;
            }
        } else {
            for (int e = tid; e < 64 * 32; e += 256) {
                int r = e >> 5, cc = e & 31;
                As[r * 36 + cc] = (cc < w) ? A[(size_t)(row0 + r) * K + kb + cc] : 0.f;
            }
        }
        __syncthreads();
#pragma unroll
        for (int k0 = 0; k0 < 32; k0 += 8) {
            uint32_t a0 = f2tf(As[(m0 + g) * 36 + k0 + q]);
            uint32_t a1 = f2tf(As[(m0 + g + 8) * 36 + k0 + q]);
            uint32_t a2 = f2tf(As[(m0 + g) * 36 + k0 + q + 4]);
            uint32_t a3 = f2tf(As[(m0 + g + 8) * 36 + k0 + q + 4]);
            int kr0 = kb + k0 + q, kr1 = kb + k0 + q + 4;
            int kc0 = kr0 < K ? kr0 : K - 1;
            int kc1 = kr1 < K ? kr1 : K - 1;
#pragma unroll
            for (int nt = 0; nt < 4; nt++) {
                int n0 = ob + nh * 32 + nt * 8;
                uint32_t b0 = f2tf(W[(size_t)kc0 * O + n0 + g]);
                uint32_t b1 = f2tf(W[(size_t)kc1 * O + n0 + g]);
                mma_tf32(d[nt], a0, a1, a2, a3, b0, b1);
            }
        }
    }
    if (which != 2) {
#pragma unroll
        for (int nt = 0; nt < 4; nt++) {
            int c0 = ob + nh * 32 + nt * 8 + q * 2;
            float bb0 = bias[c0], bb1 = bias[c0 + 1];
            float v00 = d[nt][0] + bb0, v01 = d[nt][1] + bb1;
            float v10 = d[nt][2] + bb0, v11 = d[nt][3] + bb1;
            if (dorelu) {
                v00 = fmaxf(v00, 0.f); v01 = fmaxf(v01, 0.f);
                v10 = fmaxf(v10, 0.f); v11 = fmaxf(v11, 0.f);
            }
            C[(size_t)(row0 + m0 + g) * O + c0] = v00;
            C[(size_t)(row0 + m0 + g) * O + c0 + 1] = v01;
            C[(size_t)(row0 + m0 + g + 8) * O + c0] = v10;
            C[(size_t)(row0 + m0 + g + 8) * O + c0 + 1] = v11;
        }
    } else {
#pragma unroll
        for (int nt = 0; nt < 4; nt++) {
            int c0l = nh * 32 + nt * 8 + q * 2;
            int c0 = ob + c0l;
            float bb0 = bias[c0], bb1 = bias[c0 + 1];
            float m0v = fmaxf(fmaxf(d[nt][0] + bb0, 0.f), fmaxf(d[nt][2] + bb0, 0.f));
            float m1v = fmaxf(fmaxf(d[nt][1] + bb1, 0.f), fmaxf(d[nt][3] + bb1, 0.f));
#pragma unroll
            for (int off = 4; off < 32; off <<= 1) {
                m0v = fmaxf(m0v, __shfl_xor_sync(0xffffffffu, m0v, off));
                m1v = fmaxf(m1v, __shfl_xor_sync(0xffffffffu, m1v, off));
            }
            if (g == 0) {
                Pms[mi * 64 + c0l] = m0v;
                Pms[mi * 64 + c0l + 1] = m1v;
            }
        }
        __syncthreads();
        if (tid < 64) {
            float m = fmaxf(fmaxf(Pms[tid], Pms[64 + tid]),
                            fmaxf(Pms[128 + tid], Pms[192 + tid]));
            g_pm[(size_t)mblk * 1024 + ob + tid] = m;
        }
    }
}

// ---------------------------------------------------------------------------
// Heads: combine 2 maxpool partials -> g; FC heads with 4-way k unroll.
// ---------------------------------------------------------------------------
__global__ __launch_bounds__(256) void heads_kernel(
    const float* __restrict__ lw1, const float* __restrict__ lb1,
    const float* __restrict__ lw2, const float* __restrict__ lb2,
    const float* __restrict__ fw1, const float* __restrict__ fb1,
    const float* __restrict__ fw2, const float* __restrict__ fb2,
    const float* __restrict__ pos_mean, const float* __restrict__ pos_std,
    const float* __restrict__ rot_mean, const float* __restrict__ rot_std,
    float* __restrict__ out) {
    const int b = blockIdx.x;
    const int tid = threadIdx.x;
    __shared__ float gs[1024], h1s[256], f1s[512], res[18], lab[2];
    for (int e = tid; e < 1024; e += 256)
        gs[e] = fmaxf(g_pm[(size_t)(b * 2) * 1024 + e],
                      g_pm[(size_t)(b * 2 + 1) * 1024 + e]);
    __syncthreads();
#pragma unroll
    for (int rep = 0; rep < 2; rep++) {
        int o = tid + rep * 256;
        float a0 = 0.f, a1 = 0.f, a2 = 0.f, a3 = 0.f;
        for (int k = 0; k < 1024; k += 4) {
            a0 += gs[k + 0] * fw1[(k + 0) * 512 + o];
            a1 += gs[k + 1] * fw1[(k + 1) * 512 + o];
            a2 += gs[k + 2] * fw1[(k + 2) * 512 + o];
            a3 += gs[k + 3] * fw1[(k + 3) * 512 + o];
        }
        f1s[o] = fmaxf(fb1[o] + ((a0 + a1) + (a2 + a3)), 0.f);
    }
    {
        int o = tid;
        float a0 = 0.f, a1 = 0.f, a2 = 0.f, a3 = 0.f;
        for (int k = 0; k < 1024; k += 4) {
            a0 += gs[k + 0] * lw1[(k + 0) * 256 + o];
            a1 += gs[k + 1] * lw1[(k + 1) * 256 + o];
            a2 += gs[k + 2] * lw1[(k + 2) * 256 + o];
            a3 += gs[k + 3] * lw1[(k + 3) * 256 + o];
        }
        h1s[o] = fmaxf(lb1[o] + ((a0 + a1) + (a2 + a3)), 0.f);
    }
    __syncthreads();
    if (tid < 18) {
        float a0 = 0.f, a1 = 0.f, a2 = 0.f, a3 = 0.f;
        for (int k = 0; k < 512; k += 4) {
            a0 += f1s[k + 0] * fw2[(k + 0) * 18 + tid];
            a1 += f1s[k + 1] * fw2[(k + 1) * 18 + tid];
            a2 += f1s[k + 2] * fw2[(k + 2) * 18 + tid];
            a3 += f1s[k + 3] * fw2[(k + 3) * 18 + tid];
        }
        res[tid] = fb2[tid] + ((a0 + a1) + (a2 + a3));
    } else if (tid < 20) {
        int j = tid - 18;
        float acc = lb2[j];
        for (int k = 0; k < 256; k++) acc += h1s[k] * lw2[k * 2 + j];
        lab[j] = 1.f / (1.f + expf(-acc));
    }
    __syncthreads();
    if (tid < 20) {
        float v;
        if (tid < 2) v = lab[tid];
        else if (tid < 5) { int i = tid - 2; v = res[i] * pos_std[i] + pos_mean[i]; }
        else if (tid < 11) { int i = tid - 5; v = res[3 + i] * rot_std[i] + rot_mean[i]; }
        else if (tid < 14) { int i = tid - 11; v = res[9 + i] * pos_std[i] + pos_mean[i]; }
        else { int i = tid - 14; v = res[12 + i] * rot_std[i] + rot_mean[i]; }
        out[b * 20 + tid] = v;
    }
}

// ---------------------------------------------------------------------------
extern "C" void kernel_launch(void* const* d_in, const int* in_sizes, int n_in,
                              void* d_out, int out_size) {
    (void)in_sizes; (void)n_in; (void)out_size;
    const float* pts = (const float*)d_in[0];
    const float* w10 = (const float*)d_in[1];  const float* b10 = (const float*)d_in[2];
    const float* w11 = (const float*)d_in[3];  const float* b11 = (const float*)d_in[4];
    const float* w12 = (const float*)d_in[5];  const float* b12 = (const float*)d_in[6];
    const float* w20 = (const float*)d_in[7];  const float* b20 = (const float*)d_in[8];
    const float* w21 = (const float*)d_in[9];  const float* b21 = (const float*)d_in[10];
    const float* w22 = (const float*)d_in[11]; const float* b22 = (const float*)d_in[12];
    const float* w30 = (const float*)d_in[13]; const float* b30 = (const float*)d_in[14];
    const float* w31 = (const float*)d_in[15]; const float* b31 = (const float*)d_in[16];
    const float* w32 = (const float*)d_in[17]; const float* b32 = (const float*)d_in[18];
    const float* lw1 = (const float*)d_in[19]; const float* lb1 = (const float*)d_in[20];
    const float* lw2 = (const float*)d_in[21]; const float* lb2 = (const float*)d_in[22];
    const float* fw1 = (const float*)d_in[23]; const float* fb1 = (const float*)d_in[24];
    const float* fw2 = (const float*)d_in[25]; const float* fb2 = (const float*)d_in[26];
    const float* pos_mean = (const float*)d_in[27];
    const float* pos_std  = (const float*)d_in[28];
    const float* rot_mean = (const float*)d_in[29];
    const float* rot_std  = (const float*)d_in[30];
    float* out = (float*)d_out;

    cudaFuncSetAttribute(fps_kernel, cudaFuncAttributeMaxDynamicSharedMemorySize,
                         FPS_SMEM + 256);
    cudaFuncSetAttribute(sa1_kernel, cudaFuncAttributeMaxDynamicSharedMemorySize,
                         SA1_SMEM + 256);
    cudaFuncSetAttribute(sa2_kernel, cudaFuncAttributeMaxDynamicSharedMemorySize,
                         SA2_SMEM + 256);

    fps_kernel<<<BATCH, 1024, FPS_SMEM>>>(pts);
    sa1_kernel<<<dim3(128, BATCH), 256, SA1_SMEM>>>(pts, w10, b10, w11, b11, w12, b12);
    gemm_mma_kernel<<<dim3(BATCH * 512 / 64, 2), 256>>>(w20 + 3 * 128, b20, 128, 128, 3, 0);
    sa2_kernel<<<dim3(64, BATCH), 256, SA2_SMEM>>>(w20, w21, b21, w22, b22);
    gemm_mma_kernel<<<dim3(BATCH * 128 / 64, 4), 256>>>(w30, b30, 259, 256, 0, 1);
    gemm_mma_kernel<<<dim3(BATCH * 128 / 64, 8), 256>>>(w31, b31, 256, 512, 1, 1);
    gemm_mma_kernel<<<dim3(BATCH * 128 / 64, 16), 256>>>(w32, b32, 512, 1024, 2, 1);
    heads_kernel<<<BATCH, 256>>>(lw1, lb1, lw2, lb2, fw1, fb1, fw2, fb2,
                                 pos_mean, pos_std, rot_mean, rot_std, out);
}

// round 15
// speedup vs baseline: 1.1826x; 1.1826x over previous
#include <cuda_runtime.h>
#include <cuda_bf16.h>
#include <stdint.h>
#include <math.h>

// ---------------------------------------------------------------------------
// PointNet++ grasp net forward. B=16, N=4096.
// repack(weights->tf32 fragment-major) -> FPS1 -> SA1 -> FPS2 -> U2(mma)
// -> SA2 -> SA3(mma, fused concat+maxpool) -> heads
// ---------------------------------------------------------------------------

#define BATCH 16
#define NPTS 4096

// exact f32 thresholds as JAX sees them (python double radius*radius -> f32)
#define R2A ((float)(0.2 * 0.2))
#define R2B ((float)(0.4 * 0.4))

// ------------------------- device scratch (static) -------------------------
__device__ __align__(16) float g_l1x[BATCH * 512 * 3];
__device__ __align__(16) float g_l1f[BATCH * 512 * 128];
__device__ __align__(16) float g_u2[BATCH * 512 * 128];   // l1f @ w20[3:] + b20
__device__ __align__(16) float g_l2x[BATCH * 128 * 3];
__device__ __align__(16) float g_l2f[BATCH * 128 * 256];
__device__ __align__(16) float g_h3a[BATCH * 128 * 256];
__device__ __align__(16) float g_h3b[BATCH * 128 * 512];
__device__ __align__(16) float g_pm[BATCH * 2 * 1024];    // 64-row maxpool partials

// Repacked weights: tf32 bits, fragment-major.
// idx = ((kb8 * (O/8) + ntile) * 2 + pair) * 32 + lane, lane = g*4+q,
// element = W[(kb8*8 + q + pair*4) * O + ntile*8 + g]  (OOB rows -> 0)
#define OFF11 0
#define OFF12 4096
#define OFF21 12288
#define OFF22 28672
#define OFF20 61440
#define OFF30 77824
#define OFF31 145408
#define OFF32 276480
#define PW_TOTAL 800768
__device__ __align__(16) uint32_t g_pw[PW_TOTAL];

// ------------------------- mma / redux helpers -----------------------------
__device__ __forceinline__ uint32_t f2tf(float v) {
    uint32_t r;
    asm("cvt.rna.tf32.f32 %0, %1;" : "=r"(r) : "f"(v));
    return r;
}
__device__ __forceinline__ void mma_tf32(float* d, uint32_t a0, uint32_t a1,
                                         uint32_t a2, uint32_t a3,
                                         uint32_t b0, uint32_t b1) {
    asm volatile(
        "mma.sync.aligned.m16n8k8.row.col.f32.tf32.tf32.f32 "
        "{%0,%1,%2,%3}, {%4,%5,%6,%7}, {%8,%9}, {%0,%1,%2,%3};"
        : "+f"(d[0]), "+f"(d[1]), "+f"(d[2]), "+f"(d[3])
        : "r"(a0), "r"(a1), "r"(a2), "r"(a3), "r"(b0), "r"(b1));
}
__device__ __forceinline__ uint32_t redux_max_u32(uint32_t v) {
    uint32_t r;
    asm("redux.sync.max.u32 %0, %1, 0xffffffff;" : "=r"(r) : "r"(v));
    return r;
}
__device__ __forceinline__ uint32_t redux_min_u32(uint32_t v) {
    uint32_t r;
    asm("redux.sync.min.u32 %0, %1, 0xffffffff;" : "=r"(r) : "r"(v));
    return r;
}

// ---------------------------------------------------------------------------
// Weight repack: gather into fragment-major tf32. One flat launch.
// ---------------------------------------------------------------------------
__device__ __forceinline__ uint32_t pack_one(const float* __restrict__ W,
                                             int rel, int K, int O) {
    int lane = rel & 31, pair = (rel >> 5) & 1, rest = rel >> 6;
    int nt = rest % (O / 8), kb = rest / (O / 8);
    int row = kb * 8 + (lane & 3) + pair * 4, col = nt * 8 + (lane >> 2);
    float v = (row < K) ? W[(size_t)row * O + col] : 0.f;
    return f2tf(v);
}

__global__ __launch_bounds__(256) void repack_kernel(
    const float* __restrict__ w11, const float* __restrict__ w12,
    const float* __restrict__ w21, const float* __restrict__ w22,
    const float* __restrict__ w20f, const float* __restrict__ w30,
    const float* __restrict__ w31, const float* __restrict__ w32) {
    int e = blockIdx.x * 256 + threadIdx.x;
    if (e >= PW_TOTAL) return;
    uint32_t v;
    if (e < OFF12)      v = pack_one(w11, e - OFF11, 64, 64);
    else if (e < OFF21) v = pack_one(w12, e - OFF12, 64, 128);
    else if (e < OFF22) v = pack_one(w21, e - OFF21, 128, 128);
    else if (e < OFF20) v = pack_one(w22, e - OFF22, 128, 256);
    else if (e < OFF30) v = pack_one(w20f, e - OFF20, 128, 128);
    else if (e < OFF31) v = pack_one(w30, e - OFF30, 259, 256);
    else if (e < OFF32) v = pack_one(w31, e - OFF31, 256, 512);
    else                v = pack_one(w32, e - OFF32, 512, 1024);
    g_pw[e] = v;
}

// ---------------------------------------------------------------------------
// FPS: one block per batch, two launches (phase 0: pts->l1x, phase 1:
// l1x->l2x). ONE barrier per iteration; redux.sync on float bits (dist >= 0
// so u32 order == float order); ties by min index — exact jnp argmax.
// ---------------------------------------------------------------------------
extern __shared__ float fps_sm[];

__global__ __launch_bounds__(1024) void fps_kernel(const float* __restrict__ pts_in,
                                                   int n, int S, int phase) {
    const int b = blockIdx.x;
    const float* p = (phase == 0 ? pts_in : g_l1x) + (size_t)b * n * 3;
    float* outxyz = (phase == 0 ? g_l1x : g_l2x);

    const int tid = threadIdx.x, BT = blockDim.x;
    float* sp = fps_sm;
    unsigned* rv = (unsigned*)(fps_sm + n * 3);
    int* ri = (int*)(rv + 64);

    for (int e = tid; e < n * 3; e += BT) sp[e] = p[e];

    const int PT = n / BT;
    float px[4], py[4], pz[4], dd[4];
#pragma unroll
    for (int k = 0; k < 4; k++) {
        if (k < PT) {
            int i = tid + k * BT;
            px[k] = p[i * 3 + 0];
            py[k] = p[i * 3 + 1];
            pz[k] = p[i * 3 + 2];
            dd[k] = 1e10f;
        }
    }
    __syncthreads();

    const int lane = tid & 31, wid = tid >> 5, nw = BT >> 5;
    const int lsel = lane & (nw - 1);
    int far = 0;

    for (int s = 0; s < S; s++) {
        const float fx = sp[far * 3 + 0], fy = sp[far * 3 + 1], fz = sp[far * 3 + 2];
        if (tid == 0) {
            float* o = outxyz + ((size_t)b * S + s) * 3;
            o[0] = fx; o[1] = fy; o[2] = fz;
        }
        float bv = -1.0f;
        int bi = 0x7fffffff;
#pragma unroll
        for (int k = 0; k < 4; k++) {
            if (k < PT) {
                float dx = __fsub_rn(px[k], fx);
                float dy = __fsub_rn(py[k], fy);
                float dz = __fsub_rn(pz[k], fz);
                float d = __fadd_rn(__fadd_rn(__fmul_rn(dx, dx), __fmul_rn(dy, dy)),
                                    __fmul_rn(dz, dz));
                float ndv = fminf(dd[k], d);
                dd[k] = ndv;
                if (ndv > bv) { bv = ndv; bi = tid + k * BT; }
            }
        }
        {
            uint32_t uv = __float_as_uint(bv);
            uint32_t vmax = redux_max_u32(uv);
            uint32_t ip = (uv == vmax) ? (uint32_t)bi : 0xffffffffu;
            uint32_t imin = redux_min_u32(ip);
            const int po = (s & 1) * 32;
            if (lane == 0) { rv[po + wid] = vmax; ri[po + wid] = (int)imin; }
        }
        __syncthreads();
        {
            const int po = (s & 1) * 32;
            uint32_t v = rv[po + lsel];
            int i2 = ri[po + lsel];
            uint32_t vmax = redux_max_u32(v);
            uint32_t ip = (v == vmax) ? (uint32_t)i2 : 0xffffffffu;
            far = (int)redux_min_u32(ip);
        }
    }
}

// ---------------------------------------------------------------------------
// SA1: FOUR groups per block (256 thr). Ball query r=0.2 ns=32 over 4096 pts
// amortized over 4 centers; L1 (3->64) scalar; L2/L3 on tf32 mma with fused
// per-group maxpool. 128 rows = 8 m16 tiles, warp = m-tile. Weights from
// fragment-major g_pw (coalesced, pre-converted).
// ---------------------------------------------------------------------------
#define P1 68
#define SA1_SMEM ((384 + 16 + 2 * 128 * P1) * 4 + 4 * 128 * 4 + 128 * 4)

extern __shared__ float sa1_sm[];

__global__ __launch_bounds__(256) void sa1_kernel(
    const float* __restrict__ pts,
    const float* __restrict__ w10, const float* __restrict__ b10,
    const float* __restrict__ b11, const float* __restrict__ b12) {
    const int sp4 = blockIdx.x;
    const int b = blockIdx.y;
    const int tid = threadIdx.x;
    const float* p = pts + (size_t)b * NPTS * 3;

    float* Ax = sa1_sm;
    float* ctr = Ax + 384;
    float* H1 = ctr + 16;
    float* H2 = H1 + 128 * P1;
    unsigned* smask = (unsigned*)(H2 + 128 * P1);
    int* sel = (int*)(smask + 512);

    if (tid < 12) ctr[tid] = g_l1x[((size_t)b * 512 + sp4 * 4) * 3 + tid];
    __syncthreads();

    const int lane = tid & 31, warp = tid >> 5;
    {
        const float ax = ctr[0], ay = ctr[1], az = ctr[2];
        const float bx = ctr[3], by = ctr[4], bz = ctr[5];
        const float cx = ctr[6], cy = ctr[7], cz = ctr[8];
        const float ex = ctr[9], ey = ctr[10], ez = ctr[11];
        for (int w = warp; w < 128; w += 8) {
            int j = w * 32 + lane;
            float x = p[j * 3 + 0], y = p[j * 3 + 1], z = p[j * 3 + 2];
            float t0, t1, t2, d0, d1, d2, d3;
            t0 = __fsub_rn(ax, x); t1 = __fsub_rn(ay, y); t2 = __fsub_rn(az, z);
            d0 = __fadd_rn(__fadd_rn(__fmul_rn(t0, t0), __fmul_rn(t1, t1)), __fmul_rn(t2, t2));
            t0 = __fsub_rn(bx, x); t1 = __fsub_rn(by, y); t2 = __fsub_rn(bz, z);
            d1 = __fadd_rn(__fadd_rn(__fmul_rn(t0, t0), __fmul_rn(t1, t1)), __fmul_rn(t2, t2));
            t0 = __fsub_rn(cx, x); t1 = __fsub_rn(cy, y); t2 = __fsub_rn(cz, z);
            d2 = __fadd_rn(__fadd_rn(__fmul_rn(t0, t0), __fmul_rn(t1, t1)), __fmul_rn(t2, t2));
            t0 = __fsub_rn(ex, x); t1 = __fsub_rn(ey, y); t2 = __fsub_rn(ez, z);
            d3 = __fadd_rn(__fadd_rn(__fmul_rn(t0, t0), __fmul_rn(t1, t1)), __fmul_rn(t2, t2));
            unsigned m0 = __ballot_sync(0xffffffffu, !(d0 > R2A));
            unsigned m1 = __ballot_sync(0xffffffffu, !(d1 > R2A));
            unsigned m2 = __ballot_sync(0xffffffffu, !(d2 > R2A));
            unsigned m3 = __ballot_sync(0xffffffffu, !(d3 > R2A));
            if (lane == 0) {
                smask[w] = m0; smask[128 + w] = m1;
                smask[256 + w] = m2; smask[384 + w] = m3;
            }
        }
    }
    __syncthreads();
    if ((tid & 63) == 0) {
        int gs = tid >> 6;
        int cnt = 0;
        for (int w = 0; w < 128 && cnt < 32; w++) {
            unsigned m = smask[gs * 128 + w];
            while (m && cnt < 32) {
                int t = __ffs(m) - 1;
                m &= m - 1;
                sel[gs * 32 + cnt++] = w * 32 + t;
            }
        }
        int c0 = sel[gs * 32];
        for (int j = cnt; j < 32; j++) sel[gs * 32 + j] = c0;
    }
    __syncthreads();
    for (int e = tid; e < 384; e += 256) {
        int n = e / 3, c = e - n * 3;
        Ax[e] = p[sel[n] * 3 + c] - ctr[(n >> 5) * 3 + c];
    }
    __syncthreads();

    // L1: 3 -> 64 for 128 rows
#pragma unroll
    for (int r = 0; r < 32; r++) {
        int lin = r * 256 + tid;
        int n = lin >> 6, o = lin & 63;
        float a = b10[o] + Ax[n * 3 + 0] * w10[o] + Ax[n * 3 + 1] * w10[64 + o] +
                  Ax[n * 3 + 2] * w10[128 + o];
        H1[n * P1 + o] = fmaxf(a, 0.f);
    }
    __syncthreads();

    const int g = lane >> 2, q = lane & 3;
    const int m0 = warp * 16;

    // L2: 128x64x64 tf32 mma -> H2 (weights: g_pw + OFF11, NT8=8)
    {
        const uint32_t* pw = g_pw + OFF11;
        float d[8][4] = {};
        for (int k0 = 0; k0 < 64; k0 += 8) {
            uint32_t a0 = f2tf(H1[(m0 + g) * P1 + k0 + q]);
            uint32_t a1 = f2tf(H1[(m0 + g + 8) * P1 + k0 + q]);
            uint32_t a2 = f2tf(H1[(m0 + g) * P1 + k0 + q + 4]);
            uint32_t a3 = f2tf(H1[(m0 + g + 8) * P1 + k0 + q + 4]);
            const int kb8 = k0 >> 3;
#pragma unroll
            for (int nt = 0; nt < 8; nt++) {
                const uint32_t* wp = pw + ((kb8 * 8 + nt) * 2) * 32 + lane;
                mma_tf32(d[nt], a0, a1, a2, a3, wp[0], wp[32]);
            }
        }
        __syncthreads();
#pragma unroll
        for (int nt = 0; nt < 8; nt++) {
            int c0 = nt * 8 + q * 2;
            float bb0 = b11[c0], bb1 = b11[c0 + 1];
            H2[(m0 + g) * P1 + c0] = fmaxf(d[nt][0] + bb0, 0.f);
            H2[(m0 + g) * P1 + c0 + 1] = fmaxf(d[nt][1] + bb1, 0.f);
            H2[(m0 + g + 8) * P1 + c0] = fmaxf(d[nt][2] + bb0, 0.f);
            H2[(m0 + g + 8) * P1 + c0 + 1] = fmaxf(d[nt][3] + bb1, 0.f);
        }
    }
    __syncthreads();

    // L3: 128x128x64 tf32 mma, two 64-col passes, fused 16-row maxpool
    float* Pm = H1;  // [8][128]
    for (int pass = 0; pass < 2; pass++) {
        const uint32_t* pw = g_pw + OFF12;
        float d[8][4] = {};
        for (int k0 = 0; k0 < 64; k0 += 8) {
            uint32_t a0 = f2tf(H2[(m0 + g) * P1 + k0 + q]);
            uint32_t a1 = f2tf(H2[(m0 + g + 8) * P1 + k0 + q]);
            uint32_t a2 = f2tf(H2[(m0 + g) * P1 + k0 + q + 4]);
            uint32_t a3 = f2tf(H2[(m0 + g + 8) * P1 + k0 + q + 4]);
            const int kb8 = k0 >> 3;
#pragma unroll
            for (int nt = 0; nt < 8; nt++) {
                int ntg = pass * 8 + nt;
                const uint32_t* wp = pw + ((kb8 * 16 + ntg) * 2) * 32 + lane;
                mma_tf32(d[nt], a0, a1, a2, a3, wp[0], wp[32]);
            }
        }
#pragma unroll
        for (int nt = 0; nt < 8; nt++) {
            float m0v = fmaxf(d[nt][0], d[nt][2]);
            float m1v = fmaxf(d[nt][1], d[nt][3]);
#pragma unroll
            for (int off = 4; off < 32; off <<= 1) {
                m0v = fmaxf(m0v, __shfl_xor_sync(0xffffffffu, m0v, off));
                m1v = fmaxf(m1v, __shfl_xor_sync(0xffffffffu, m1v, off));
            }
            if (g == 0) {
                int c0 = pass * 64 + nt * 8 + q * 2;
                Pm[warp * 128 + c0] = m0v;
                Pm[warp * 128 + c0 + 1] = m1v;
            }
        }
    }
    __syncthreads();
    for (int e = tid; e < 512; e += 256) {
        int h = e >> 7, o = e & 127;
        float m = fmaxf(Pm[(2 * h) * 128 + o], Pm[(2 * h + 1) * 128 + o]);
        g_l1f[((size_t)b * 512 + sp4 * 4 + h) * 128 + o] = fmaxf(m + b12[o], 0.f);
    }
}

// ---------------------------------------------------------------------------
// SA2: TWO groups per block (128 rows). Ball query r=0.4 ns=64 over 512 pts;
// L1 via U2 gather; L2/L3 on tf32 mma with fragment-major weights.
// ---------------------------------------------------------------------------
#define P2 132
#define SA2_SMEM ((128 * P2 + 8 * 256 + 8 + 384) * 4 + 32 * 4 + 128 * 4)

extern __shared__ float sa2_sm[];

__global__ __launch_bounds__(256) void sa2_kernel(
    const float* __restrict__ w20,
    const float* __restrict__ b21, const float* __restrict__ b22) {
    const int s2 = blockIdx.x;  // groups s2*2, s2*2+1
    const int b = blockIdx.y;
    const int tid = threadIdx.x;
    const float* px = g_l1x + (size_t)b * 512 * 3;

    float* H = sa2_sm;
    float* Pm = H + 128 * P2;
    float* ctr = Pm + 8 * 256;
    float* dx3 = ctr + 8;
    unsigned* smask = (unsigned*)(dx3 + 384);
    int* sel = (int*)(smask + 32);

    if (tid < 6) ctr[tid] = g_l2x[((size_t)b * 128 + s2 * 2) * 3 + tid];
    __syncthreads();

    const int lane = tid & 31, warp = tid >> 5;
    {
        const float ax = ctr[0], ay = ctr[1], az = ctr[2];
        const float bx = ctr[3], by = ctr[4], bz = ctr[5];
        for (int w = warp; w < 16; w += 8) {
            int j = w * 32 + lane;
            float x = px[j * 3 + 0], y = px[j * 3 + 1], z = px[j * 3 + 2];
            float t0, t1, t2, d0, d1;
            t0 = __fsub_rn(ax, x); t1 = __fsub_rn(ay, y); t2 = __fsub_rn(az, z);
            d0 = __fadd_rn(__fadd_rn(__fmul_rn(t0, t0), __fmul_rn(t1, t1)), __fmul_rn(t2, t2));
            t0 = __fsub_rn(bx, x); t1 = __fsub_rn(by, y); t2 = __fsub_rn(bz, z);
            d1 = __fadd_rn(__fadd_rn(__fmul_rn(t0, t0), __fmul_rn(t1, t1)), __fmul_rn(t2, t2));
            unsigned m0 = __ballot_sync(0xffffffffu, !(d0 > R2B));
            unsigned m1 = __ballot_sync(0xffffffffu, !(d1 > R2B));
            if (lane == 0) { smask[w] = m0; smask[16 + w] = m1; }
        }
    }
    __syncthreads();
    if (tid == 0 || tid == 128) {
        int gs = tid >> 7;
        int cnt = 0;
        for (int w = 0; w < 16 && cnt < 64; w++) {
            unsigned m = smask[gs * 16 + w];
            while (m && cnt < 64) {
                int t = __ffs(m) - 1;
                m &= m - 1;
                sel[gs * 64 + cnt++] = w * 32 + t;
            }
        }
        int c0 = sel[gs * 64];
        for (int j = cnt; j < 64; j++) sel[gs * 64 + j] = c0;
    }
    __syncthreads();
    for (int e = tid; e < 384; e += 256) {
        int n = e / 3, c = e - n * 3;
        dx3[e] = px[sel[n] * 3 + c] - ctr[(n >> 6) * 3 + c];
    }
    __syncthreads();

    // L1: gather U2 + xyz contribution, relu. 16 rows x 4 cols per thread.
    {
        const int o0 = (tid & 31) * 4, n0 = (tid >> 5) * 16;
        float4 wxv = *(const float4*)(w20 + o0);
        float4 wyv = *(const float4*)(w20 + 128 + o0);
        float4 wzv = *(const float4*)(w20 + 256 + o0);
#pragma unroll
        for (int i = 0; i < 16; i++) {
            int n = n0 + i;
            float ddx = dx3[n * 3 + 0], ddy = dx3[n * 3 + 1], ddz = dx3[n * 3 + 2];
            float4 u = *(const float4*)(g_u2 + ((size_t)b * 512 + sel[n]) * 128 + o0);
            float4 r;
            r.x = fmaxf(u.x + ddx * wxv.x + ddy * wyv.x + ddz * wzv.x, 0.f);
            r.y = fmaxf(u.y + ddx * wxv.y + ddy * wyv.y + ddz * wzv.y, 0.f);
            r.z = fmaxf(u.z + ddx * wxv.z + ddy * wyv.z + ddz * wzv.z, 0.f);
            r.w = fmaxf(u.w + ddx * wxv.w + ddy * wyv.w + ddz * wzv.w, 0.f);
            *(float4*)(H + n * P2 + o0) = r;
        }
    }
    __syncthreads();

    const int g = lane >> 2, q = lane & 3;
    const int m0 = warp * 16;

    // L2: 128x128x128 tf32 mma (warp = m-tile, full 128 cols), in-place H
    {
        const uint32_t* pw = g_pw + OFF21;
        float d[16][4] = {};
        for (int k0 = 0; k0 < 128; k0 += 8) {
            uint32_t a0 = f2tf(H[(m0 + g) * P2 + k0 + q]);
            uint32_t a1 = f2tf(H[(m0 + g + 8) * P2 + k0 + q]);
            uint32_t a2 = f2tf(H[(m0 + g) * P2 + k0 + q + 4]);
            uint32_t a3 = f2tf(H[(m0 + g + 8) * P2 + k0 + q + 4]);
            const int kb8 = k0 >> 3;
#pragma unroll
            for (int nt = 0; nt < 16; nt++) {
                const uint32_t* wp = pw + ((kb8 * 16 + nt) * 2) * 32 + lane;
                mma_tf32(d[nt], a0, a1, a2, a3, wp[0], wp[32]);
            }
        }
        __syncthreads();
#pragma unroll
        for (int nt = 0; nt < 16; nt++) {
            int c0 = nt * 8 + q * 2;
            float bb0 = b21[c0], bb1 = b21[c0 + 1];
            H[(m0 + g) * P2 + c0] = fmaxf(d[nt][0] + bb0, 0.f);
            H[(m0 + g) * P2 + c0 + 1] = fmaxf(d[nt][1] + bb1, 0.f);
            H[(m0 + g + 8) * P2 + c0] = fmaxf(d[nt][2] + bb0, 0.f);
            H[(m0 + g + 8) * P2 + c0 + 1] = fmaxf(d[nt][3] + bb1, 0.f);
        }
    }
    __syncthreads();

    // L3: 128x256x128 tf32 mma, two 128-col passes, fused 16-row maxpool
    for (int pass = 0; pass < 2; pass++) {
        const uint32_t* pw = g_pw + OFF22;
        float d[16][4] = {};
        for (int k0 = 0; k0 < 128; k0 += 8) {
            uint32_t a0 = f2tf(H[(m0 + g) * P2 + k0 + q]);
            uint32_t a1 = f2tf(H[(m0 + g + 8) * P2 + k0 + q]);
            uint32_t a2 = f2tf(H[(m0 + g) * P2 + k0 + q + 4]);
            uint32_t a3 = f2tf(H[(m0 + g + 8) * P2 + k0 + q + 4]);
            const int kb8 = k0 >> 3;
#pragma unroll
            for (int nt = 0; nt < 16; nt++) {
                int ntg = pass * 16 + nt;
                const uint32_t* wp = pw + ((kb8 * 32 + ntg) * 2) * 32 + lane;
                mma_tf32(d[nt], a0, a1, a2, a3, wp[0], wp[32]);
            }
        }
#pragma unroll
        for (int nt = 0; nt < 16; nt++) {
            float m0v = fmaxf(d[nt][0], d[nt][2]);
            float m1v = fmaxf(d[nt][1], d[nt][3]);
#pragma unroll
            for (int off = 4; off < 32; off <<= 1) {
                m0v = fmaxf(m0v, __shfl_xor_sync(0xffffffffu, m0v, off));
                m1v = fmaxf(m1v, __shfl_xor_sync(0xffffffffu, m1v, off));
            }
            if (g == 0) {
                int c0 = pass * 128 + nt * 8 + q * 2;
                Pm[warp * 256 + c0] = m0v;
                Pm[warp * 256 + c0 + 1] = m1v;
            }
        }
    }
    __syncthreads();
    for (int e = tid; e < 512; e += 256) {
        int h = e >> 8, o = e & 255;
        float m = fmaxf(fmaxf(Pm[(4 * h) * 256 + o], Pm[(4 * h + 1) * 256 + o]),
                        fmaxf(Pm[(4 * h + 2) * 256 + o], Pm[(4 * h + 3) * 256 + o]));
        g_l2f[((size_t)b * 128 + s2 * 2 + h) * 256 + o] = fmaxf(m + b22[o], 0.f);
    }
}

// ---------------------------------------------------------------------------
// tf32 mma GEMM + bias (+relu), batch flattened into M, fragment-major
// weights from g_pw. which: 0 concat(l2x,l2f)->h3a (K=259,O=256, KB=33),
// 1 h3a->h3b (256,512), 2 h3b->g_pm maxpool partials (512,1024),
// 3 l1f->u2 (128,128).
// ---------------------------------------------------------------------------
__global__ __launch_bounds__(256) void gemm_mma_kernel(const float* __restrict__ bias,
                                                       int K, int O, int which, int dorelu) {
    const int mblk = blockIdx.x, oblk = blockIdx.y;
    const float* A = nullptr;
    float* C = nullptr;
    const uint32_t* pw;
    if (which == 1) { A = g_h3a; C = g_h3b; pw = g_pw + OFF31; }
    else if (which == 2) { A = g_h3b; pw = g_pw + OFF32; }
    else if (which == 3) { A = g_l1f; C = g_u2; pw = g_pw + OFF20; }
    else { C = g_h3a; pw = g_pw + OFF30; }
    const int KB = (K + 7) >> 3, NT8 = O >> 3;

    const int row0 = mblk * 64;
    const int tid = threadIdx.x, lane = tid & 31, warp = tid >> 5;
    const int g = lane >> 2, q = lane & 3;
    const int mi = warp >> 1, nh = warp & 1, m0 = mi * 16;
    const int ob = oblk * 64;

    __shared__ __align__(16) float As[64 * 36];
    __shared__ float Pms[4 * 64];
    float d[4][4] = {};
    for (int kb = 0; kb < K; kb += 32) {
        const int w = min(32, K - kb);
        __syncthreads();
        if (which == 0) {
            for (int e = tid; e < 64 * 32; e += 256) {
                int r = e >> 5, cc = e & 31;
                int col = kb + cc;
                float v = 0.f;
                if (col < K) {
                    int row = row0 + r, bb = row >> 7, nn = row & 127;
                    v = (col < 3) ? g_l2x[((size_t)bb * 128 + nn) * 3 + col]
                                  : g_l2f[((size_t)bb * 128 + nn) * 256 + col - 3];
                }
                As[r * 36 + cc] = v;
            }
        } else {
            for (int e = tid; e < 64 * 32; e += 256) {
                int r = e >> 5, cc = e & 31;
                As[r * 36 + cc] = (cc < w) ? A[(size_t)(row0 + r) * K + kb + cc] : 0.f;
            }
        }
        __syncthreads();
#pragma unroll
        for (int k0 = 0; k0 < 32; k0 += 8) {
            uint32_t a0 = f2tf(As[(m0 + g) * 36 + k0 + q]);
            uint32_t a1 = f2tf(As[(m0 + g + 8) * 36 + k0 + q]);
            uint32_t a2 = f2tf(As[(m0 + g) * 36 + k0 + q + 4]);
            uint32_t a3 = f2tf(As[(m0 + g + 8) * 36 + k0 + q + 4]);
            const int kb8 = (kb + k0) >> 3;
            const bool kok = kb8 < KB;
#pragma unroll
            for (int nt = 0; nt < 4; nt++) {
                int ntg = (ob >> 3) + nh * 4 + nt;
                uint32_t b0 = 0u, b1 = 0u;
                if (kok) {
                    const uint32_t* wp = pw + ((kb8 * NT8 + ntg) * 2) * 32 + lane;
                    b0 = wp[0]; b1 = wp[32];
                }
                mma_tf32(d[nt], a0, a1, a2, a3, b0, b1);
            }
        }
    }
    if (which != 2) {
#pragma unroll
        for (int nt = 0; nt < 4; nt++) {
            int c0 = ob + nh * 32 + nt * 8 + q * 2;
            float bb0 = bias[c0], bb1 = bias[c0 + 1];
            float v00 = d[nt][0] + bb0, v01 = d[nt][1] + bb1;
            float v10 = d[nt][2] + bb0, v11 = d[nt][3] + bb1;
            if (dorelu) {
                v00 = fmaxf(v00, 0.f); v01 = fmaxf(v01, 0.f);
                v10 = fmaxf(v10, 0.f); v11 = fmaxf(v11, 0.f);
            }
            C[(size_t)(row0 + m0 + g) * O + c0] = v00;
            C[(size_t)(row0 + m0 + g) * O + c0 + 1] = v01;
            C[(size_t)(row0 + m0 + g + 8) * O + c0] = v10;
            C[(size_t)(row0 + m0 + g + 8) * O + c0 + 1] = v11;
        }
    } else {
#pragma unroll
        for (int nt = 0; nt < 4; nt++) {
            int c0l = nh * 32 + nt * 8 + q * 2;
            int c0 = ob + c0l;
            float bb0 = bias[c0], bb1 = bias[c0 + 1];
            float m0v = fmaxf(fmaxf(d[nt][0] + bb0, 0.f), fmaxf(d[nt][2] + bb0, 0.f));
            float m1v = fmaxf(fmaxf(d[nt][1] + bb1, 0.f), fmaxf(d[nt][3] + bb1, 0.f));
#pragma unroll
            for (int off = 4; off < 32; off <<= 1) {
                m0v = fmaxf(m0v, __shfl_xor_sync(0xffffffffu, m0v, off));
                m1v = fmaxf(m1v, __shfl_xor_sync(0xffffffffu, m1v, off));
            }
            if (g == 0) {
                Pms[mi * 64 + c0l] = m0v;
                Pms[mi * 64 + c0l + 1] = m1v;
            }
        }
        __syncthreads();
        if (tid < 64) {
            float m = fmaxf(fmaxf(Pms[tid], Pms[64 + tid]),
                            fmaxf(Pms[128 + tid], Pms[192 + tid]));
            g_pm[(size_t)mblk * 1024 + ob + tid] = m;
        }
    }
}

// ---------------------------------------------------------------------------
// Heads: combine 2 maxpool partials -> g; FC heads with 4-way k unroll.
// ---------------------------------------------------------------------------
__global__ __launch_bounds__(256) void heads_kernel(
    const float* __restrict__ lw1, const float* __restrict__ lb1,
    const float* __restrict__ lw2, const float* __restrict__ lb2,
    const float* __restrict__ fw1, const float* __restrict__ fb1,
    const float* __restrict__ fw2, const float* __restrict__ fb2,
    const float* __restrict__ pos_mean, const float* __restrict__ pos_std,
    const float* __restrict__ rot_mean, const float* __restrict__ rot_std,
    float* __restrict__ out) {
    const int b = blockIdx.x;
    const int tid = threadIdx.x;
    __shared__ float gs[1024], h1s[256], f1s[512], res[18], lab[2];
    for (int e = tid; e < 1024; e += 256)
        gs[e] = fmaxf(g_pm[(size_t)(b * 2) * 1024 + e],
                      g_pm[(size_t)(b * 2 + 1) * 1024 + e]);
    __syncthreads();
#pragma unroll
    for (int rep = 0; rep < 2; rep++) {
        int o = tid + rep * 256;
        float acc = fb1[o];
        for (int k = 0; k < 1024; k++) acc += gs[k] * fw1[k * 512 + o];
        f1s[o] = fmaxf(acc, 0.f);
    }
    {
        int o = tid;
        float acc = lb1[o];
        for (int k = 0; k < 1024; k++) acc += gs[k] * lw1[k * 256 + o];
        h1s[o] = fmaxf(acc, 0.f);
    }
    __syncthreads();
    if (tid < 18) {
        float acc = fb2[tid];
        for (int k = 0; k < 512; k++) acc += f1s[k] * fw2[k * 18 + tid];
        res[tid] = acc;
    } else if (tid < 20) {
        int j = tid - 18;
        float acc = lb2[j];
        for (int k = 0; k < 256; k++) acc += h1s[k] * lw2[k * 2 + j];
        lab[j] = 1.f / (1.f + expf(-acc));
    }
    __syncthreads();
    if (tid < 20) {
        float v;
        if (tid < 2) v = lab[tid];
        else if (tid < 5) { int i = tid - 2; v = res[i] * pos_std[i] + pos_mean[i]; }
        else if (tid < 11) { int i = tid - 5; v = res[3 + i] * rot_std[i] + rot_mean[i]; }
        else if (tid < 14) { int i = tid - 11; v = res[9 + i] * pos_std[i] + pos_mean[i]; }
        else { int i = tid - 14; v = res[12 + i] * rot_std[i] + rot_mean[i]; }
        out[b * 20 + tid] = v;
    }
}

// ---------------------------------------------------------------------------
extern "C" void kernel_launch(void* const* d_in, const int* in_sizes, int n_in,
                              void* d_out, int out_size) {
    (void)in_sizes; (void)n_in; (void)out_size;
    const float* pts = (const float*)d_in[0];
    const float* w10 = (const float*)d_in[1];  const float* b10 = (const float*)d_in[2];
    const float* w11 = (const float*)d_in[3];  const float* b11 = (const float*)d_in[4];
    const float* w12 = (const float*)d_in[5];  const float* b12 = (const float*)d_in[6];
    const float* w20 = (const float*)d_in[7];  const float* b20 = (const float*)d_in[8];
    const float* w21 = (const float*)d_in[9];  const float* b21 = (const float*)d_in[10];
    const float* w22 = (const float*)d_in[11]; const float* b22 = (const float*)d_in[12];
    const float* w30 = (const float*)d_in[13]; const float* b30 = (const float*)d_in[14];
    const float* w31 = (const float*)d_in[15]; const float* b31 = (const float*)d_in[16];
    const float* w32 = (const float*)d_in[17]; const float* b32 = (const float*)d_in[18];
    const float* lw1 = (const float*)d_in[19]; const float* lb1 = (const float*)d_in[20];
    const float* lw2 = (const float*)d_in[21]; const float* lb2 = (const float*)d_in[22];
    const float* fw1 = (const float*)d_in[23]; const float* fb1 = (const float*)d_in[24];
    const float* fw2 = (const float*)d_in[25]; const float* fb2 = (const float*)d_in[26];
    const float* pos_mean = (const float*)d_in[27];
    const float* pos_std  = (const float*)d_in[28];
    const float* rot_mean = (const float*)d_in[29];
    const float* rot_std  = (const float*)d_in[30];
    float* out = (float*)d_out;

    cudaFuncSetAttribute(fps_kernel, cudaFuncAttributeMaxDynamicSharedMemorySize,
                         NPTS * 3 * 4 + 1024);
    cudaFuncSetAttribute(sa1_kernel, cudaFuncAttributeMaxDynamicSharedMemorySize,
                         SA1_SMEM + 256);
    cudaFuncSetAttribute(sa2_kernel, cudaFuncAttributeMaxDynamicSharedMemorySize,
                         SA2_SMEM + 256);

    repack_kernel<<<(PW_TOTAL + 255) / 256, 256>>>(w11, w12, w21, w22,
                                                   w20 + 3 * 128, w30, w31, w32);
    fps_kernel<<<BATCH, 1024, NPTS * 3 * 4 + 768>>>(pts, NPTS, 512, 0);
    sa1_kernel<<<dim3(128, BATCH), 256, SA1_SMEM>>>(pts, w10, b10, b11, b12);
    fps_kernel<<<BATCH, 512, 512 * 3 * 4 + 768>>>(pts, 512, 128, 1);
    gemm_mma_kernel<<<dim3(BATCH * 512 / 64, 2), 256>>>(b20, 128, 128, 3, 0);
    sa2_kernel<<<dim3(64, BATCH), 256, SA2_SMEM>>>(w20, b21, b22);
    gemm_mma_kernel<<<dim3(BATCH * 128 / 64, 4), 256>>>(b30, 259, 256, 0, 1);
    gemm_mma_kernel<<<dim3(BATCH * 128 / 64, 8), 256>>>(b31, 256, 512, 1, 1);
    gemm_mma_kernel<<<dim3(BATCH * 128 / 64, 16), 256>>>(b32, 512, 1024, 2, 1);
    heads_kernel<<<BATCH, 256>>>(lw1, lb1, lw2, lb2, fw1, fb1, fw2, fb2,
                                 pos_mean, pos_std, rot_mean, rot_std, out);
}